// round 12
// baseline (speedup 1.0000x reference)
#include <cuda_runtime.h>
#include <cuda_bf16.h>
#include <math.h>

#define NGOI 500
#define SUMH 224
#define SUMW 221
#define SUMG 56   // SUMH/4 granules
#define L2E  1.4426950408889634f

// Gene-level precomputed tables (per layer blocks).
// g_lA[k]   = log2(A_k),  A_k = H_k * c_k          (length n per gene)
// g_blg2[m] = {bl[4m], bl[4m+4] or +BIG}           (length n/4 per gene)
// g_fbl[m]  = {bl[4m],bl[4m+1],bl[4m+2],bl[4m+3]}  (length n/4 per gene)
// g_bin[b]  = {1/c_b, 1/c_{b+1}, w_b, bl_b}        (length n-1 per gene)
__device__ __align__(16) float  g_lA[NGOI * SUMH];    // 448 KB
__device__ __align__(16) float2 g_blg2[NGOI * SUMG];  // 224 KB
__device__ __align__(16) float4 g_fbl[NGOI * SUMG];   // 448 KB
__device__ __align__(16) float4 g_bin[NGOI * SUMW];   // 1.77 MB

// ---------------------------------------------------------------------------
// Precompute: one warp per (gene, layer), 8 warps per block.
// ---------------------------------------------------------------------------
__global__ __launch_bounds__(256) void precompute_kernel(
    const float* __restrict__ hw,
    const float* __restrict__ ww,
    const int* __restrict__ goi)
{
    const int NB[3]   = {128, 64, 32};
    const int WOFF[3] = {0, 127, 190};
    const int HOFF[3] = {0, 128, 192};
    const int AOFF[3] = {0, NGOI * 128, NGOI * 192};
    const int GOFF[3] = {0, NGOI * 32,  NGOI * 48};
    const int BOFF[3] = {0, NGOI * 127, NGOI * 190};

    int gw = (blockIdx.x * blockDim.x + threadIdx.x) >> 5;   // global warp id
    if (gw >= NGOI * 3) return;
    int g = gw % NGOI;
    int l = gw / NGOI;
    int wslot = (threadIdx.x >> 5);
    int lane = threadIdx.x & 31;
    int n = NB[l];
    int E = n >> 5;
    int gid = goi[g];
    const float* uw = ww + (size_t)gid * SUMW + WOFF[l];
    const float* uh = hw + (size_t)gid * SUMH + HOFF[l];

    __shared__ float sw[8][128];
    __shared__ float sbl[8][128];
    __shared__ float sH[8][128];
    float* swp  = sw[wslot];
    float* sblp = sbl[wslot];
    float* sHp  = sH[wslot];
    const unsigned FM = 0xffffffffu;

    float u[4], ex[4];
    float m = -1e30f;
    for (int j = 0; j < E; j++) {
        int k = j * 32 + lane;
        u[j] = (k < n - 1) ? uw[k] : -1e30f;
        m = fmaxf(m, u[j]);
    }
    for (int o = 16; o; o >>= 1) m = fmaxf(m, __shfl_xor_sync(FM, m, o));

    float s = 0.f;
    for (int j = 0; j < E; j++) {
        int k = j * 32 + lane;
        ex[j] = (k < n - 1) ? expf(u[j] - m) : 0.f;
        s += ex[j];
    }
    for (int o = 16; o; o >>= 1) s += __shfl_xor_sync(FM, s, o);
    float inv = 1.f / s;

    // inclusive cumsum over k = j*32 + lane ordering
    float base = 0.f;
    for (int j = 0; j < E; j++) {
        int k = j * 32 + lane;
        float v = ex[j] * inv;            // w_k (0 for k == n-1 slot)
        float t = v;
        for (int o = 1; o < 32; o <<= 1) {
            float q = __shfl_up_sync(FM, t, o);
            if (lane >= o) t += q;
        }
        t += base;
        base = __shfl_sync(FM, t, 31);
        if (k < n - 1) { swp[k] = v; sblp[k + 1] = t; }
    }
    __syncwarp();
    if (lane == 0) { sblp[0] = 0.f; sblp[n - 1] = 1.0f; }  // ref forces last cumsum to 1
    __syncwarp();

    for (int j = 0; j < E; j++) {
        int k = j * 32 + lane;
        sHp[k] = expf(uh[k]);
    }
    __syncwarp();

    float*  lAout = g_lA  + AOFF[l] + g * n;
    float4* bin   = g_bin + BOFF[l] + g * (n - 1);
    for (int j = 0; j < E; j++) {
        int k = j * 32 + lane;
        float wkm1 = (k >= 1)     ? swp[k - 1] : 0.f;
        float wk   = (k < n - 1)  ? swp[k]     : 0.f;
        float c  = 0.5f * (wkm1 + wk);
        lAout[k] = log2f(sHp[k] * c);
        if (k < n - 1) {
            float wk1 = (k + 1 < n - 1) ? swp[k + 1] : 0.f;
            float c1  = 0.5f * (wk + wk1);           // c_{k+1}
            bin[k] = make_float4(1.0f / c, 1.0f / c1, swp[k], sblp[k]);
        }
    }
    int ng = n >> 2;
    if (lane < ng) {
        int mg = lane;
        float nxt = (mg < ng - 1) ? sblp[4 * mg + 4] : 3.0e38f;
        g_blg2[GOFF[l] + g * ng + mg] = make_float2(sblp[4 * mg], nxt);
        g_fbl[GOFF[l] + g * ng + mg] =
            make_float4(sblp[4 * mg], sblp[4 * mg + 1], sblp[4 * mg + 2], sblp[4 * mg + 3]);
    }
}

// ---------------------------------------------------------------------------
// Main: 4 lanes per point, 8 points per warp. Granule m = j*4 + sl covers
// bins [4m, 4m+4). cnt/full/part all accumulate in the main loop (shifted-
// boundary mask makes part x-maskable in-flight); single 2-step, 3-value
// segmented butterfly. Epilogue recomputes the b-granule from L1-hot lines.
// ---------------------------------------------------------------------------
template <int N>
__device__ __forceinline__ void spline_layer(
    float& x, float& lad, int g, int sl,
    const float* __restrict__ dptr,
    const float* __restrict__ lAbase,
    const float2* __restrict__ blg2base,
    const float4* __restrict__ fblbase,
    const float4* __restrict__ binbase)
{
    constexpr int NG = N / 4;            // granules per layer
    constexpr int IT = NG / 4;           // iterations per lane (4 lanes/point)
    constexpr unsigned FM = 0xffffffffu;

    const float*  lA  = lAbase + g * N;
    const float4* lAv = reinterpret_cast<const float4*>(lA);
    const float4* Dv  = reinterpret_cast<const float4*>(dptr);
    const float2* b2  = blg2base + g * NG;

    float full = 0.f, part = 0.f;
    int cnt = 0;
#pragma unroll
    for (int j = 0; j < IT; j++) {
        int mg = j * 4 + sl;
        float4 la = __ldg(lAv + mg);
        float4 d  = __ldg(Dv + mg);
        float2 bb = __ldg(b2 + mg);
        float t0 = exp2f(fmaf(d.x, L2E, la.x));
        float t1 = exp2f(fmaf(d.y, L2E, la.y));
        float t2 = exp2f(fmaf(d.z, L2E, la.z));
        float t3 = exp2f(fmaf(d.w, L2E, la.w));
        float s = (t0 + t1) + (t2 + t3);
        full += s;
        cnt += (x >= bb.x);
        if (x >= bb.y) part += s;        // granule strictly before b's granule
    }

    // segmented (width-4) butterfly: cnt, full, part together
#pragma unroll
    for (int o = 2; o; o >>= 1) {
        cnt  += __shfl_xor_sync(FM, cnt,  o);
        full += __shfl_xor_sync(FM, full, o);
        part += __shfl_xor_sync(FM, part, o);
    }
    int gidx = cnt - 1;                  // cnt >= 1 since bl[0] = 0 <= x

    // fine refinement within granule (uniform per segment)
    float4 f = __ldg(fblbase + g * NG + gidx);
    int r = (x >= f.y) + (x >= f.z) + (x >= f.w);
    int b = gidx * 4 + r;
    if (b > N - 2) { b = N - 2; r = 2; } // only case: gidx=NG-1, r=3

    // recompute b-granule terms from L1-hot lines (uniform per segment)
    float4 la = __ldg(lAv + gidx);
    float4 d  = __ldg(Dv + gidx);
    float e0 = exp2f(fmaf(d.x, L2E, la.x));
    float e1 = exp2f(fmaf(d.y, L2E, la.y));
    float e2 = exp2f(fmaf(d.z, L2E, la.z));
    float e3 = exp2f(fmaf(d.w, L2E, la.w));
    part += e0;                          // k = 4*gidx <= b always
    if (r >= 1) part += e1;
    if (r >= 2) part += e2;
    if (r >= 3) part += e3;

    // e'_b = A_b*Ed_b and e'_{b+1}
    float ebp = (r < 2) ? (r ? e1 : e0) : ((r == 3) ? e3 : e2);
    float ebp1;
    if (r < 3) ebp1 = (r == 0) ? e1 : ((r == 1) ? e2 : e3);
    else ebp1 = exp2f(fmaf(__ldg(dptr + b + 1), L2E, __ldg(lA + b + 1)));

    float4 sc = __ldg(binbase + g * (N - 1) + b);    // {1/c_b, 1/c_{b+1}, w_b, bl_b}
    float eb  = ebp * sc.x;              // H_b * Ed_b
    float eb1 = ebp1 * sc.y;             // H_{b+1} * Ed_{b+1}
    float wb  = sc.z;
    float blb = sc.w;

    float ra  = __fdividef(1.f, full);
    float in_cdf = (part - 0.5f * eb * wb) * ra;
    float hl = eb * ra;
    float hr = eb1 * ra;
    float alpha = __fdividef(x - blb, wb);
    float dhh = hr - hl;
    float out = fmaf(fmaf(0.5f * dhh * wb, alpha, hl * wb), alpha, in_cdf);
    out = fminf(fmaxf(out, 0.f), 1.f);
    lad += __logf(fmaf(alpha, dhh, hl));
    x = out;
}

__global__ __launch_bounds__(256) void spline_main(
    const float* __restrict__ xin,
    const float* __restrict__ delta,
    const int* __restrict__ lgi,
    float* __restrict__ out,
    int n_points)
{
    int warp = (blockIdx.x * blockDim.x + threadIdx.x) >> 5;
    int lane = threadIdx.x & 31;
    int seg  = lane >> 2;        // 0..7 : point within warp
    int sl   = lane & 3;         // 0..3 : lane within point

    int p = warp * 8 + seg;
    int nwarps = (n_points + 7) >> 3;
    if (warp >= nwarps) return;              // whole warp exits together
    int pc = min(p, n_points - 1);           // clamp: keep all lanes converged

    const float* dptr = delta + (size_t)pc * SUMH;

    // L2-prefetch the full 896B delta row: 4 lanes x (224,224+112)B offsets
    // touch all 7 cache lines of the row. Two instrs, zero registers.
    asm volatile("prefetch.global.L2 [%0];"
                 :: "l"(reinterpret_cast<const char*>(dptr) + sl * 224));
    asm volatile("prefetch.global.L2 [%0];"
                 :: "l"(reinterpret_cast<const char*>(dptr) + sl * 224 + 112));

    float x = __ldg(xin + pc);
    int g = __ldg(lgi + pc);
    float lad = 0.f;

    spline_layer<128>(x, lad, g, sl, dptr,
                      g_lA,              g_blg2,             g_fbl,             g_bin);
    spline_layer<64> (x, lad, g, sl, dptr + 128,
                      g_lA + NGOI * 128, g_blg2 + NGOI * 32, g_fbl + NGOI * 32, g_bin + NGOI * 127);
    spline_layer<32> (x, lad, g, sl, dptr + 192,
                      g_lA + NGOI * 192, g_blg2 + NGOI * 48, g_fbl + NGOI * 48, g_bin + NGOI * 190);

    if (p < n_points) {
        if (sl == 0) out[p] = x;
        if (sl == 1) out[n_points + p] = lad;
    }
}

extern "C" void kernel_launch(void* const* d_in, const int* in_sizes, int n_in,
                              void* d_out, int out_size)
{
    const float* x     = (const float*)d_in[0];
    const float* delta = (const float*)d_in[1];
    const float* hw    = (const float*)d_in[2];
    const float* ww    = (const float*)d_in[3];
    const int*   goi   = (const int*)d_in[4];
    const int*   lgi   = (const int*)d_in[5];
    float* out = (float*)d_out;
    int n = in_sizes[0];

    int pwarps = NGOI * 3;
    precompute_kernel<<<(pwarps * 32 + 255) / 256, 256>>>(hw, ww, goi);

    int nwarps = (n + 7) / 8;                 // 8 points per warp
    int blocks = (nwarps * 32 + 255) / 256;
    spline_main<<<blocks, 256>>>(x, delta, lgi, out, n);
}

// round 14
// speedup vs baseline: 1.1694x; 1.1694x over previous
#include <cuda_runtime.h>
#include <cuda_bf16.h>
#include <math.h>

#define NGOI 500
#define SUMH 224
#define SUMW 221
#define SUMG 56   // SUMH/4 granules
#define L2E  1.4426950408889634f

// Gene-level precomputed tables (per layer blocks).
// g_lA[k]   = log2(A_k),  A_k = H_k * c_k          (length n per gene)
// g_blg2[m] = {bl[4m], bl[4m+4] or +BIG}           (length n/4 per gene)
// g_fbl[m]  = {bl[4m],bl[4m+1],bl[4m+2],bl[4m+3]}  (length n/4 per gene)
// g_bin[b]  = {1/c_b, 1/c_{b+1}, w_b, bl_b}        (length n-1 per gene)
__device__ __align__(16) float  g_lA[NGOI * SUMH];    // 448 KB
__device__ __align__(16) float2 g_blg2[NGOI * SUMG];  // 224 KB
__device__ __align__(16) float4 g_fbl[NGOI * SUMG];   // 448 KB
__device__ __align__(16) float4 g_bin[NGOI * SUMW];   // 1.77 MB

// ---------------------------------------------------------------------------
// Precompute: one warp per (gene, layer), 8 warps per block.
// ---------------------------------------------------------------------------
__global__ __launch_bounds__(256) void precompute_kernel(
    const float* __restrict__ hw,
    const float* __restrict__ ww,
    const int* __restrict__ goi)
{
    const int NB[3]   = {128, 64, 32};
    const int WOFF[3] = {0, 127, 190};
    const int HOFF[3] = {0, 128, 192};
    const int AOFF[3] = {0, NGOI * 128, NGOI * 192};
    const int GOFF[3] = {0, NGOI * 32,  NGOI * 48};
    const int BOFF[3] = {0, NGOI * 127, NGOI * 190};

    int gw = (blockIdx.x * blockDim.x + threadIdx.x) >> 5;   // global warp id
    if (gw >= NGOI * 3) return;
    int g = gw % NGOI;
    int l = gw / NGOI;
    int wslot = (threadIdx.x >> 5);
    int lane = threadIdx.x & 31;
    int n = NB[l];
    int E = n >> 5;
    int gid = goi[g];
    const float* uw = ww + (size_t)gid * SUMW + WOFF[l];
    const float* uh = hw + (size_t)gid * SUMH + HOFF[l];

    __shared__ float sw[8][128];
    __shared__ float sbl[8][128];
    __shared__ float sH[8][128];
    float* swp  = sw[wslot];
    float* sblp = sbl[wslot];
    float* sHp  = sH[wslot];
    const unsigned FM = 0xffffffffu;

    float u[4], ex[4];
    float m = -1e30f;
    for (int j = 0; j < E; j++) {
        int k = j * 32 + lane;
        u[j] = (k < n - 1) ? uw[k] : -1e30f;
        m = fmaxf(m, u[j]);
    }
    for (int o = 16; o; o >>= 1) m = fmaxf(m, __shfl_xor_sync(FM, m, o));

    float s = 0.f;
    for (int j = 0; j < E; j++) {
        int k = j * 32 + lane;
        ex[j] = (k < n - 1) ? expf(u[j] - m) : 0.f;
        s += ex[j];
    }
    for (int o = 16; o; o >>= 1) s += __shfl_xor_sync(FM, s, o);
    float inv = 1.f / s;

    // inclusive cumsum over k = j*32 + lane ordering
    float base = 0.f;
    for (int j = 0; j < E; j++) {
        int k = j * 32 + lane;
        float v = ex[j] * inv;            // w_k (0 for k == n-1 slot)
        float t = v;
        for (int o = 1; o < 32; o <<= 1) {
            float q = __shfl_up_sync(FM, t, o);
            if (lane >= o) t += q;
        }
        t += base;
        base = __shfl_sync(FM, t, 31);
        if (k < n - 1) { swp[k] = v; sblp[k + 1] = t; }
    }
    __syncwarp();
    if (lane == 0) { sblp[0] = 0.f; sblp[n - 1] = 1.0f; }  // ref forces last cumsum to 1
    __syncwarp();

    for (int j = 0; j < E; j++) {
        int k = j * 32 + lane;
        sHp[k] = expf(uh[k]);
    }
    __syncwarp();

    float*  lAout = g_lA  + AOFF[l] + g * n;
    float4* bin   = g_bin + BOFF[l] + g * (n - 1);
    for (int j = 0; j < E; j++) {
        int k = j * 32 + lane;
        float wkm1 = (k >= 1)     ? swp[k - 1] : 0.f;
        float wk   = (k < n - 1)  ? swp[k]     : 0.f;
        float c  = 0.5f * (wkm1 + wk);
        lAout[k] = log2f(sHp[k] * c);
        if (k < n - 1) {
            float wk1 = (k + 1 < n - 1) ? swp[k + 1] : 0.f;
            float c1  = 0.5f * (wk + wk1);           // c_{k+1}
            bin[k] = make_float4(1.0f / c, 1.0f / c1, swp[k], sblp[k]);
        }
    }
    int ng = n >> 2;
    if (lane < ng) {
        int mg = lane;
        float nxt = (mg < ng - 1) ? sblp[4 * mg + 4] : 3.0e38f;
        g_blg2[GOFF[l] + g * ng + mg] = make_float2(sblp[4 * mg], nxt);
        g_fbl[GOFF[l] + g * ng + mg] =
            make_float4(sblp[4 * mg], sblp[4 * mg + 1], sblp[4 * mg + 2], sblp[4 * mg + 3]);
    }
}

// ---------------------------------------------------------------------------
// Main: 8 lanes per point, 4 points per warp (R10 layout). Granule
// m = j*8 + sl covers bins [4m, 4m+4). cnt/full/part all accumulate in the
// main loop (shifted-boundary mask); single 3-step, 3-value segmented
// butterfly. Epilogue recomputes the b-granule from L1-hot lines.
// ---------------------------------------------------------------------------
template <int N>
__device__ __forceinline__ void spline_layer(
    float& x, float& lad, int g, int sl,
    const float* __restrict__ dptr,
    const float* __restrict__ lAbase,
    const float2* __restrict__ blg2base,
    const float4* __restrict__ fblbase,
    const float4* __restrict__ binbase)
{
    constexpr int NG = N / 4;            // granules per layer
    constexpr int IT = NG / 8;           // iterations per lane (8 lanes/point)
    constexpr unsigned FM = 0xffffffffu;

    const float*  lA  = lAbase + g * N;
    const float4* lAv = reinterpret_cast<const float4*>(lA);
    const float4* Dv  = reinterpret_cast<const float4*>(dptr);
    const float2* b2  = blg2base + g * NG;

    float full = 0.f, part = 0.f;
    int cnt = 0;
#pragma unroll
    for (int j = 0; j < IT; j++) {
        int mg = j * 8 + sl;
        float4 la = __ldg(lAv + mg);
        float4 d  = __ldg(Dv + mg);
        float2 bb = __ldg(b2 + mg);
        float t0 = exp2f(fmaf(d.x, L2E, la.x));
        float t1 = exp2f(fmaf(d.y, L2E, la.y));
        float t2 = exp2f(fmaf(d.z, L2E, la.z));
        float t3 = exp2f(fmaf(d.w, L2E, la.w));
        float s = (t0 + t1) + (t2 + t3);
        full += s;
        cnt += (x >= bb.x);
        if (x >= bb.y) part += s;        // granule strictly before b's granule
    }

    // segmented (width-8) butterfly: cnt, full, part together
#pragma unroll
    for (int o = 4; o; o >>= 1) {
        cnt  += __shfl_xor_sync(FM, cnt,  o);
        full += __shfl_xor_sync(FM, full, o);
        part += __shfl_xor_sync(FM, part, o);
    }
    int gidx = cnt - 1;                  // cnt >= 1 since bl[0] = 0 <= x

    // fine refinement within granule (uniform per segment)
    float4 f = __ldg(fblbase + g * NG + gidx);
    int r = (x >= f.y) + (x >= f.z) + (x >= f.w);
    int b = gidx * 4 + r;
    if (b > N - 2) { b = N - 2; r = 2; } // only case: gidx=NG-1, r=3

    // recompute b-granule terms from L1-hot lines (uniform per segment)
    float4 la = __ldg(lAv + gidx);
    float4 d  = __ldg(Dv + gidx);
    float e0 = exp2f(fmaf(d.x, L2E, la.x));
    float e1 = exp2f(fmaf(d.y, L2E, la.y));
    float e2 = exp2f(fmaf(d.z, L2E, la.z));
    float e3 = exp2f(fmaf(d.w, L2E, la.w));
    part += e0;                          // k = 4*gidx <= b always
    if (r >= 1) part += e1;
    if (r >= 2) part += e2;
    if (r >= 3) part += e3;

    // e'_b = A_b*Ed_b and e'_{b+1}
    float ebp = (r < 2) ? (r ? e1 : e0) : ((r == 3) ? e3 : e2);
    float ebp1;
    if (r < 3) ebp1 = (r == 0) ? e1 : ((r == 1) ? e2 : e3);
    else ebp1 = exp2f(fmaf(__ldg(dptr + b + 1), L2E, __ldg(lA + b + 1)));

    float4 sc = __ldg(binbase + g * (N - 1) + b);    // {1/c_b, 1/c_{b+1}, w_b, bl_b}
    float eb  = ebp * sc.x;              // H_b * Ed_b
    float eb1 = ebp1 * sc.y;             // H_{b+1} * Ed_{b+1}
    float wb  = sc.z;
    float blb = sc.w;

    float ra  = __fdividef(1.f, full);
    float in_cdf = (part - 0.5f * eb * wb) * ra;
    float hl = eb * ra;
    float hr = eb1 * ra;
    float alpha = __fdividef(x - blb, wb);
    float dhh = hr - hl;
    float out = fmaf(fmaf(0.5f * dhh * wb, alpha, hl * wb), alpha, in_cdf);
    out = fminf(fmaxf(out, 0.f), 1.f);
    lad += __logf(fmaf(alpha, dhh, hl));
    x = out;
}

__global__ __launch_bounds__(256) void spline_main(
    const float* __restrict__ xin,
    const float* __restrict__ delta,
    const int* __restrict__ lgi,
    float* __restrict__ out,
    int n_points)
{
    int warp = (blockIdx.x * blockDim.x + threadIdx.x) >> 5;
    int lane = threadIdx.x & 31;
    int seg  = lane >> 3;        // 0..3 : point within warp
    int sl   = lane & 7;         // 0..7 : lane within point

    int p = warp * 4 + seg;
    int nwarps = (n_points + 3) >> 2;
    if (warp >= nwarps) return;              // whole warp exits together
    int pc = min(p, n_points - 1);           // clamp: keep all lanes converged

    const float* dptr = delta + (size_t)pc * SUMH;

    // L2-prefetch the full 896B delta row: 8 lanes x 112B stride touches
    // every 128B line of the row. One warp instruction, zero registers.
    asm volatile("prefetch.global.L2 [%0];"
                 :: "l"(reinterpret_cast<const char*>(dptr) + sl * 112));

    float x = __ldg(xin + pc);
    int g = __ldg(lgi + pc);
    float lad = 0.f;

    spline_layer<128>(x, lad, g, sl, dptr,
                      g_lA,              g_blg2,             g_fbl,             g_bin);
    spline_layer<64> (x, lad, g, sl, dptr + 128,
                      g_lA + NGOI * 128, g_blg2 + NGOI * 32, g_fbl + NGOI * 32, g_bin + NGOI * 127);
    spline_layer<32> (x, lad, g, sl, dptr + 192,
                      g_lA + NGOI * 192, g_blg2 + NGOI * 48, g_fbl + NGOI * 48, g_bin + NGOI * 190);

    if (p < n_points) {
        if (sl == 0) out[p] = x;
        if (sl == 1) out[n_points + p] = lad;
    }
}

extern "C" void kernel_launch(void* const* d_in, const int* in_sizes, int n_in,
                              void* d_out, int out_size)
{
    const float* x     = (const float*)d_in[0];
    const float* delta = (const float*)d_in[1];
    const float* hw    = (const float*)d_in[2];
    const float* ww    = (const float*)d_in[3];
    const int*   goi   = (const int*)d_in[4];
    const int*   lgi   = (const int*)d_in[5];
    float* out = (float*)d_out;
    int n = in_sizes[0];

    int pwarps = NGOI * 3;
    precompute_kernel<<<(pwarps * 32 + 255) / 256, 256>>>(hw, ww, goi);

    int nwarps = (n + 3) / 4;                 // 4 points per warp
    int blocks = (nwarps * 32 + 255) / 256;
    spline_main<<<blocks, 256>>>(x, delta, lgi, out, n);
}